// round 1
// baseline (speedup 1.0000x reference)
#include <cuda_runtime.h>
#include <math.h>

// ---------------------------------------------------------------------------
// CrossModalFusion: q=rgb@Wq+bq; k,v=pose@W{k,v}+b; scores=q k^T/sqrt(512);
// attn=softmax; out=attn v; proj=out@Wp+bp; fused=LN(rgb+gate*proj)
// B=32, S=2048, D=400, H=512
// ---------------------------------------------------------------------------

#define B_   32
#define S_   2048
#define D_   400
#define H_   512

// __device__ scratch (allocation-free requirement)
__device__ float g_q   [(long)B_*S_*H_];   // [b][s][h]
__device__ float g_k   [(long)B_*S_*H_];   // [b][s][h]
__device__ float g_vT  [(long)B_*H_*S_];   // [b][h][s]
__device__ float g_att [(long)B_*S_*S_];   // [b][q][k]  (scores -> attn in place)
__device__ float g_out [(long)B_*S_*H_];   // [b][q][h]
__device__ float g_proj[(long)B_*S_*D_];   // [b][q][d]
__device__ float g_WqT [H_*D_];
__device__ float g_WkT [H_*D_];
__device__ float g_WvT [H_*D_];
__device__ float g_WpT [D_*H_];

// ---------------------------------------------------------------------------
// tiny transpose: out[c*R + r] = in[r*C + c]
// ---------------------------------------------------------------------------
__global__ void transpose_k(const float* __restrict__ in, float* __restrict__ out,
                            int R, int C) {
    int idx = blockIdx.x * blockDim.x + threadIdx.x;
    if (idx < R * C) {
        int r = idx / C, c = idx % C;
        out[c * R + r] = in[idx];
    }
}

// ---------------------------------------------------------------------------
// Generic NT GEMM: C[m][n] = alpha * sum_k A[m][k]*B[n][k]  (+bias_n[n]) (+bias_m[m])
// A: [M,K] row-major (lda=K), B: [N,K] row-major (ldb=K), C: [M,N] row-major (ldc=N)
// Batched via blockIdx.z with element strides sA,sB,sC.
// Tile: 64x64x16, 256 threads, 4x4 per thread.
// Requires: M % 64 == 0, K % 16 == 0. N handled with guards.
// ---------------------------------------------------------------------------
__global__ void __launch_bounds__(256)
gemm_nt(const float* __restrict__ A, long sA,
        const float* __restrict__ B, long sB,
        float* __restrict__ C, long sC,
        int M, int N, int K, float alpha,
        const float* __restrict__ bias_n,
        const float* __restrict__ bias_m) {
    __shared__ float As[16][68];
    __shared__ float Bs[16][68];

    const int tid = threadIdx.x;
    const long b = blockIdx.z;
    A += b * sA; B += b * sB; C += b * sC;

    const int m0 = blockIdx.y * 64;
    const int n0 = blockIdx.x * 64;

    const int lr = tid >> 2;          // 0..63 tile row
    const int lc = (tid & 3) * 4;     // 0,4,8,12 k offset
    const int ty = tid >> 4;          // 0..15
    const int tx = tid & 15;          // 0..15

    const float* Aptr = A + (long)(m0 + lr) * K + lc;
    const bool bval = (n0 + lr) < N;
    const float* Bptr = B + (long)(n0 + lr) * K + lc;

    float acc[4][4];
#pragma unroll
    for (int i = 0; i < 4; i++)
#pragma unroll
        for (int j = 0; j < 4; j++) acc[i][j] = 0.f;

    for (int k0 = 0; k0 < K; k0 += 16) {
        float4 av = *(const float4*)(Aptr + k0);
        float4 bv = bval ? *(const float4*)(Bptr + k0) : make_float4(0.f, 0.f, 0.f, 0.f);
        As[lc + 0][lr] = av.x; As[lc + 1][lr] = av.y;
        As[lc + 2][lr] = av.z; As[lc + 3][lr] = av.w;
        Bs[lc + 0][lr] = bv.x; Bs[lc + 1][lr] = bv.y;
        Bs[lc + 2][lr] = bv.z; Bs[lc + 3][lr] = bv.w;
        __syncthreads();
#pragma unroll
        for (int k = 0; k < 16; k++) {
            float4 a4 = *(const float4*)&As[k][ty * 4];
            float4 b4 = *(const float4*)&Bs[k][tx * 4];
            float ar[4] = {a4.x, a4.y, a4.z, a4.w};
            float br[4] = {b4.x, b4.y, b4.z, b4.w};
#pragma unroll
            for (int i = 0; i < 4; i++)
#pragma unroll
                for (int j = 0; j < 4; j++) acc[i][j] += ar[i] * br[j];
        }
        __syncthreads();
    }

#pragma unroll
    for (int i = 0; i < 4; i++) {
        int row = m0 + ty * 4 + i;
        float bm = bias_m ? bias_m[row] : 0.f;
#pragma unroll
        for (int j = 0; j < 4; j++) {
            int col = n0 + tx * 4 + j;
            if (col < N) {
                float v = acc[i][j] * alpha + bm;
                if (bias_n) v += bias_n[col];
                C[(long)row * N + col] = v;
            }
        }
    }
}

// ---------------------------------------------------------------------------
// Row softmax over fixed 2048 columns; one block (256 thr) per row, in place.
// ---------------------------------------------------------------------------
__global__ void __launch_bounds__(256)
softmax2048(float* __restrict__ data) {
    float* row = data + (long)blockIdx.x * 2048;
    const int tid = threadIdx.x;
    __shared__ float red[8];

    float v[8];
    float m = -3.4e38f;
#pragma unroll
    for (int i = 0; i < 8; i++) { v[i] = row[tid + i * 256]; m = fmaxf(m, v[i]); }
#pragma unroll
    for (int o = 16; o > 0; o >>= 1) m = fmaxf(m, __shfl_xor_sync(~0u, m, o));
    if ((tid & 31) == 0) red[tid >> 5] = m;
    __syncthreads();
    float rowmax = red[0];
#pragma unroll
    for (int w = 1; w < 8; w++) rowmax = fmaxf(rowmax, red[w]);
    __syncthreads();

    float s = 0.f;
#pragma unroll
    for (int i = 0; i < 8; i++) { v[i] = __expf(v[i] - rowmax); s += v[i]; }
#pragma unroll
    for (int o = 16; o > 0; o >>= 1) s += __shfl_xor_sync(~0u, s, o);
    if ((tid & 31) == 0) red[tid >> 5] = s;
    __syncthreads();
    float tot = 0.f;
#pragma unroll
    for (int w = 0; w < 8; w++) tot += red[w];
    float inv = 1.f / tot;
#pragma unroll
    for (int i = 0; i < 8; i++) row[tid + i * 256] = v[i] * inv;
}

// ---------------------------------------------------------------------------
// Fused residual + LayerNorm over last dim (400). One block (128 thr) per row.
// ---------------------------------------------------------------------------
__global__ void __launch_bounds__(128)
ln_epilogue(const float* __restrict__ proj, const float* __restrict__ rgb,
            const float* __restrict__ gate, const float* __restrict__ gamma,
            const float* __restrict__ beta, float* __restrict__ out) {
    const long row = blockIdx.x;
    const int tid = threadIdx.x;
    const float g = gate[0];
    __shared__ float xs[D_];
    __shared__ float red[4];

    float s = 0.f;
    for (int i = tid; i < D_; i += 128) {
        float x = rgb[row * D_ + i] + g * proj[row * D_ + i];
        xs[i] = x;
        s += x;
    }
#pragma unroll
    for (int o = 16; o > 0; o >>= 1) s += __shfl_xor_sync(~0u, s, o);
    if ((tid & 31) == 0) red[tid >> 5] = s;
    __syncthreads();
    float mu = (red[0] + red[1] + red[2] + red[3]) * (1.0f / D_);
    __syncthreads();

    float vs = 0.f;
    for (int i = tid; i < D_; i += 128) {
        float d = xs[i] - mu;
        vs += d * d;
    }
#pragma unroll
    for (int o = 16; o > 0; o >>= 1) vs += __shfl_xor_sync(~0u, vs, o);
    if ((tid & 31) == 0) red[tid >> 5] = vs;
    __syncthreads();
    float var = (red[0] + red[1] + red[2] + red[3]) * (1.0f / D_);
    float inv = rsqrtf(var + 1e-5f);

    for (int i = tid; i < D_; i += 128) {
        out[row * D_ + i] = (xs[i] - mu) * inv * gamma[i] + beta[i];
    }
}

// ---------------------------------------------------------------------------
static float* sym(const void* s) {
    void* p = nullptr;
    cudaGetSymbolAddress(&p, s);
    return (float*)p;
}

extern "C" void kernel_launch(void* const* d_in, const int* in_sizes, int n_in,
                              void* d_out, int out_size) {
    const float* rgb   = (const float*)d_in[0];
    const float* pose  = (const float*)d_in[1];
    const float* Wq    = (const float*)d_in[2];
    const float* bq    = (const float*)d_in[3];
    const float* Wk    = (const float*)d_in[4];
    const float* bk    = (const float*)d_in[5];
    const float* Wv    = (const float*)d_in[6];
    const float* bv    = (const float*)d_in[7];
    const float* Wp    = (const float*)d_in[8];
    const float* bp    = (const float*)d_in[9];
    const float* gamma = (const float*)d_in[10];
    const float* beta  = (const float*)d_in[11];
    const float* gate  = (const float*)d_in[12];
    float* out = (float*)d_out;

    float* q    = sym(g_q);
    float* k    = sym(g_k);
    float* vT   = sym(g_vT);
    float* att  = sym(g_att);
    float* o    = sym(g_out);
    float* proj = sym(g_proj);
    float* WqT  = sym(g_WqT);
    float* WkT  = sym(g_WkT);
    float* WvT  = sym(g_WvT);
    float* WpT  = sym(g_WpT);

    const int MS = B_ * S_;               // 65536
    const float inv_sqrt_h = 0.044194173824159216f;  // 1/sqrt(512)

    // weight transposes
    {
        int n1 = D_ * H_;
        transpose_k<<<(n1 + 255) / 256, 256>>>(Wq, WqT, D_, H_);
        transpose_k<<<(n1 + 255) / 256, 256>>>(Wk, WkT, D_, H_);
        transpose_k<<<(n1 + 255) / 256, 256>>>(Wv, WvT, D_, H_);
        transpose_k<<<(n1 + 255) / 256, 256>>>(Wp, WpT, H_, D_);
    }

    // q = rgb @ Wq + bq    : A=rgb [65536,400], B=WqT [512,400]
    gemm_nt<<<dim3(H_ / 64, MS / 64, 1), 256>>>(
        rgb, 0, WqT, 0, q, 0, MS, H_, D_, 1.f, bq, nullptr);
    // k = pose @ Wk + bk
    gemm_nt<<<dim3(H_ / 64, MS / 64, 1), 256>>>(
        pose, 0, WkT, 0, k, 0, MS, H_, D_, 1.f, bk, nullptr);
    // vT[b][h][s] = (pose @ Wv + bv)^T : A=WvT [512,400], B=pose_b [2048,400]
    gemm_nt<<<dim3(S_ / 64, H_ / 64, B_), 256>>>(
        WvT, 0, pose, (long)S_ * D_, vT, (long)H_ * S_,
        H_, S_, D_, 1.f, nullptr, bv);

    // scores[b][q][k] = q_b . k_b / sqrt(H)
    gemm_nt<<<dim3(S_ / 64, S_ / 64, B_), 256>>>(
        q, (long)S_ * H_, k, (long)S_ * H_, att, (long)S_ * S_,
        S_, S_, H_, inv_sqrt_h, nullptr, nullptr);

    // softmax rows
    softmax2048<<<B_ * S_, 256>>>(att);

    // out[b][q][h] = attn_b @ v_b  (NT vs vT)
    gemm_nt<<<dim3(H_ / 64, S_ / 64, B_), 256>>>(
        att, (long)S_ * S_, vT, (long)H_ * S_, o, (long)S_ * H_,
        S_, H_, S_, 1.f, nullptr, nullptr);

    // proj = out @ Wp + bp : A=out [65536,512], B=WpT [400,512]
    gemm_nt<<<dim3((D_ + 63) / 64, MS / 64, 1), 256>>>(
        o, 0, WpT, 0, proj, 0, MS, D_, H_, 1.f, bp, nullptr);

    // fused = LN(rgb + gate*proj)
    ln_epilogue<<<B_ * S_, 128>>>(proj, rgb, gate, gamma, beta, out);
}

// round 2
// speedup vs baseline: 3.5918x; 3.5918x over previous
#include <cuda_runtime.h>
#include <math.h>

#define B_   32
#define S_   2048
#define D_   400
#define H_   512

// __device__ scratch (allocation-free requirement)
__device__ float g_q   [(long)B_*S_*H_];   // [b][s][h]
__device__ float g_k   [(long)B_*S_*H_];   // [b][s][h]
__device__ float g_vT  [(long)B_*H_*S_];   // [b][h][s]
__device__ float g_att [(long)B_*S_*S_];   // [b][q][k]
__device__ float g_out [(long)B_*S_*H_];   // [b][q][h]
__device__ float g_proj[(long)B_*S_*D_];   // [b][q][d]
__device__ float g_WqT [H_*D_];
__device__ float g_WkT [H_*D_];
__device__ float g_WvT [H_*D_];
__device__ float g_WpT [D_*H_];

// ---------------------------------------------------------------------------
__global__ void transpose_k(const float* __restrict__ in, float* __restrict__ out,
                            int R, int C) {
    int idx = blockIdx.x * blockDim.x + threadIdx.x;
    if (idx < R * C) {
        int r = idx / C, c = idx % C;
        out[c * R + r] = in[idx];
    }
}

// ---------------------------------------------------------------------------
__device__ __forceinline__ unsigned f2tf32(float x) {
    unsigned u;
    asm("cvt.rna.tf32.f32 %0, %1;" : "=r"(u) : "f"(x));
    return u;
}

#define SMEM_LD 20   // 16 k-floats + 8-float pad => (20*g + tg) mod 32 conflict-free

// ---------------------------------------------------------------------------
// NT GEMM on tensor cores (tf32 mma.sync m16n8k8):
// C[m][n] = alpha * sum_k A[m][k]*B[n][k] (+bias_n[n]) (+bias_m[m])
// Block 128x128x16, 256 thr (8 warps, 2x4 grid of 64x32 warp tiles),
// cp.async double buffer. Requires M%128==0, K%16==0; N tail guarded.
// ---------------------------------------------------------------------------
__global__ void __launch_bounds__(256, 2)
gemm_tf32(const float* __restrict__ A, long sA,
          const float* __restrict__ B, long sB,
          float* __restrict__ C, long sC,
          int M, int N, int K, float alpha,
          const float* __restrict__ bias_n,
          const float* __restrict__ bias_m) {
    __shared__ float As[2][128 * SMEM_LD];
    __shared__ float Bs[2][128 * SMEM_LD];

    const int tid  = threadIdx.x;
    const int lane = tid & 31;
    const int wid  = tid >> 5;
    const int wr   = wid & 1;        // warp row (0..1) -> 64 rows each
    const int wc   = wid >> 1;       // warp col (0..3) -> 32 cols each
    const int g    = lane >> 2;      // groupID
    const int tg   = lane & 3;       // threadID_in_group

    const long bz = blockIdx.z;
    A += bz * sA; B += bz * sB; C += bz * sC;
    const int m0 = blockIdx.y * 128;
    const int n0 = blockIdx.x * 128;

    // copy mapping: 256 thr, each does 2 rows (r, r+64), one float4 of k
    const int ldr = tid >> 2;            // 0..63
    const int ldc = (tid & 3) * 4;       // 0,4,8,12

    const float* Ag0 = A + (long)(m0 + ldr) * K + ldc;
    const float* Ag1 = Ag0 + (long)64 * K;
    const int bn0 = n0 + ldr;
    const bool v0 = bn0 < N, v1 = (bn0 + 64) < N;
    const float* Bg0 = B + (long)(v0 ? bn0 : 0) * K + ldc;
    const float* Bg1 = B + (long)(v1 ? bn0 + 64 : 0) * K + ldc;
    const unsigned z0 = v0 ? 16u : 0u, z1 = v1 ? 16u : 0u;

    unsigned sa[2], sb[2];
    sa[0] = (unsigned)__cvta_generic_to_shared(&As[0][ldr * SMEM_LD + ldc]);
    sa[1] = (unsigned)__cvta_generic_to_shared(&As[1][ldr * SMEM_LD + ldc]);
    sb[0] = (unsigned)__cvta_generic_to_shared(&Bs[0][ldr * SMEM_LD + ldc]);
    sb[1] = (unsigned)__cvta_generic_to_shared(&Bs[1][ldr * SMEM_LD + ldc]);
    const unsigned off64 = 64 * SMEM_LD * 4;

    float acc[4][4][4];
#pragma unroll
    for (int i = 0; i < 4; i++)
#pragma unroll
        for (int j = 0; j < 4; j++)
#pragma unroll
            for (int c = 0; c < 4; c++) acc[i][j][c] = 0.f;

    const int T = K / 16;

    // prologue: stage 0
    asm volatile("cp.async.cg.shared.global [%0], [%1], 16;\n" :: "r"(sa[0]), "l"(Ag0));
    asm volatile("cp.async.cg.shared.global [%0], [%1], 16;\n" :: "r"(sa[0] + off64), "l"(Ag1));
    asm volatile("cp.async.cg.shared.global [%0], [%1], 16, %2;\n" :: "r"(sb[0]), "l"(Bg0), "r"(z0));
    asm volatile("cp.async.cg.shared.global [%0], [%1], 16, %2;\n" :: "r"(sb[0] + off64), "l"(Bg1), "r"(z1));
    asm volatile("cp.async.commit_group;\n");

    for (int t = 0; t < T; t++) {
        const int buf = t & 1;
        if (t + 1 < T) {
            const int nb = buf ^ 1;
            const long k0 = (long)(t + 1) * 16;
            asm volatile("cp.async.cg.shared.global [%0], [%1], 16;\n" :: "r"(sa[nb]), "l"(Ag0 + k0));
            asm volatile("cp.async.cg.shared.global [%0], [%1], 16;\n" :: "r"(sa[nb] + off64), "l"(Ag1 + k0));
            asm volatile("cp.async.cg.shared.global [%0], [%1], 16, %2;\n" :: "r"(sb[nb]), "l"(Bg0 + k0), "r"(z0));
            asm volatile("cp.async.cg.shared.global [%0], [%1], 16, %2;\n" :: "r"(sb[nb] + off64), "l"(Bg1 + k0), "r"(z1));
            asm volatile("cp.async.commit_group;\n");
            asm volatile("cp.async.wait_group 1;\n");
        } else {
            asm volatile("cp.async.wait_group 0;\n");
        }
        __syncthreads();

#pragma unroll
        for (int kk = 0; kk < 16; kk += 8) {
            unsigned af[4][4], bf[4][2];
#pragma unroll
            for (int i = 0; i < 4; i++) {
                const float* p = &As[buf][(wr * 64 + i * 16 + g) * SMEM_LD + kk + tg];
                af[i][0] = f2tf32(p[0]);
                af[i][1] = f2tf32(p[8 * SMEM_LD]);
                af[i][2] = f2tf32(p[4]);
                af[i][3] = f2tf32(p[8 * SMEM_LD + 4]);
            }
#pragma unroll
            for (int j = 0; j < 4; j++) {
                const float* p = &Bs[buf][(wc * 32 + j * 8 + g) * SMEM_LD + kk + tg];
                bf[j][0] = f2tf32(p[0]);
                bf[j][1] = f2tf32(p[4]);
            }
#pragma unroll
            for (int i = 0; i < 4; i++)
#pragma unroll
                for (int j = 0; j < 4; j++) {
                    asm volatile(
                        "mma.sync.aligned.m16n8k8.row.col.f32.tf32.tf32.f32 "
                        "{%0,%1,%2,%3}, {%4,%5,%6,%7}, {%8,%9}, {%0,%1,%2,%3};\n"
                        : "+f"(acc[i][j][0]), "+f"(acc[i][j][1]),
                          "+f"(acc[i][j][2]), "+f"(acc[i][j][3])
                        : "r"(af[i][0]), "r"(af[i][1]), "r"(af[i][2]), "r"(af[i][3]),
                          "r"(bf[j][0]), "r"(bf[j][1]));
                }
        }
        __syncthreads();
    }

    // epilogue (N even always; c0/c0+1 pair is in or out together)
#pragma unroll
    for (int i = 0; i < 4; i++) {
        const int r0 = m0 + wr * 64 + i * 16 + g;
        const int r1 = r0 + 8;
        const float bm0 = bias_m ? bias_m[r0] : 0.f;
        const float bm1 = bias_m ? bias_m[r1] : 0.f;
#pragma unroll
        for (int j = 0; j < 4; j++) {
            const int c0 = n0 + wc * 32 + j * 8 + 2 * tg;
            if (c0 < N) {
                const float bnl = bias_n ? bias_n[c0]     : 0.f;
                const float bnh = bias_n ? bias_n[c0 + 1] : 0.f;
                float2 lo = make_float2(acc[i][j][0] * alpha + bm0 + bnl,
                                        acc[i][j][1] * alpha + bm0 + bnh);
                float2 hi = make_float2(acc[i][j][2] * alpha + bm1 + bnl,
                                        acc[i][j][3] * alpha + bm1 + bnh);
                *(float2*)&C[(long)r0 * N + c0] = lo;
                *(float2*)&C[(long)r1 * N + c0] = hi;
            }
        }
    }
}

// ---------------------------------------------------------------------------
__global__ void __launch_bounds__(256)
softmax2048(float* __restrict__ data) {
    float* row = data + (long)blockIdx.x * 2048;
    const int tid = threadIdx.x;
    __shared__ float red[8];

    float v[8];
    float m = -3.4e38f;
#pragma unroll
    for (int i = 0; i < 8; i++) { v[i] = row[tid + i * 256]; m = fmaxf(m, v[i]); }
#pragma unroll
    for (int o = 16; o > 0; o >>= 1) m = fmaxf(m, __shfl_xor_sync(~0u, m, o));
    if ((tid & 31) == 0) red[tid >> 5] = m;
    __syncthreads();
    float rowmax = red[0];
#pragma unroll
    for (int w = 1; w < 8; w++) rowmax = fmaxf(rowmax, red[w]);
    __syncthreads();

    float s = 0.f;
#pragma unroll
    for (int i = 0; i < 8; i++) { v[i] = __expf(v[i] - rowmax); s += v[i]; }
#pragma unroll
    for (int o = 16; o > 0; o >>= 1) s += __shfl_xor_sync(~0u, s, o);
    if ((tid & 31) == 0) red[tid >> 5] = s;
    __syncthreads();
    float tot = 0.f;
#pragma unroll
    for (int w = 0; w < 8; w++) tot += red[w];
    float inv = 1.f / tot;
#pragma unroll
    for (int i = 0; i < 8; i++) row[tid + i * 256] = v[i] * inv;
}

// ---------------------------------------------------------------------------
__global__ void __launch_bounds__(128)
ln_epilogue(const float* __restrict__ proj, const float* __restrict__ rgb,
            const float* __restrict__ gate, const float* __restrict__ gamma,
            const float* __restrict__ beta, float* __restrict__ out) {
    const long row = blockIdx.x;
    const int tid = threadIdx.x;
    const float g = gate[0];
    __shared__ float xs[D_];
    __shared__ float red[4];

    float s = 0.f;
    for (int i = tid; i < D_; i += 128) {
        float x = rgb[row * D_ + i] + g * proj[row * D_ + i];
        xs[i] = x;
        s += x;
    }
#pragma unroll
    for (int o = 16; o > 0; o >>= 1) s += __shfl_xor_sync(~0u, s, o);
    if ((tid & 31) == 0) red[tid >> 5] = s;
    __syncthreads();
    float mu = (red[0] + red[1] + red[2] + red[3]) * (1.0f / D_);
    __syncthreads();

    float vs = 0.f;
    for (int i = tid; i < D_; i += 128) {
        float d = xs[i] - mu;
        vs += d * d;
    }
#pragma unroll
    for (int o = 16; o > 0; o >>= 1) vs += __shfl_xor_sync(~0u, vs, o);
    if ((tid & 31) == 0) red[tid >> 5] = vs;
    __syncthreads();
    float var = (red[0] + red[1] + red[2] + red[3]) * (1.0f / D_);
    float inv = rsqrtf(var + 1e-5f);

    for (int i = tid; i < D_; i += 128) {
        out[row * D_ + i] = (xs[i] - mu) * inv * gamma[i] + beta[i];
    }
}

// ---------------------------------------------------------------------------
static float* sym(const void* s) {
    void* p = nullptr;
    cudaGetSymbolAddress(&p, s);
    return (float*)p;
}

extern "C" void kernel_launch(void* const* d_in, const int* in_sizes, int n_in,
                              void* d_out, int out_size) {
    const float* rgb   = (const float*)d_in[0];
    const float* pose  = (const float*)d_in[1];
    const float* Wq    = (const float*)d_in[2];
    const float* bq    = (const float*)d_in[3];
    const float* Wk    = (const float*)d_in[4];
    const float* bk    = (const float*)d_in[5];
    const float* Wv    = (const float*)d_in[6];
    const float* bv    = (const float*)d_in[7];
    const float* Wp    = (const float*)d_in[8];
    const float* bp    = (const float*)d_in[9];
    const float* gamma = (const float*)d_in[10];
    const float* beta  = (const float*)d_in[11];
    const float* gate  = (const float*)d_in[12];
    float* out = (float*)d_out;

    float* q    = sym(g_q);
    float* k    = sym(g_k);
    float* vT   = sym(g_vT);
    float* att  = sym(g_att);
    float* o    = sym(g_out);
    float* proj = sym(g_proj);
    float* WqT  = sym(g_WqT);
    float* WkT  = sym(g_WkT);
    float* WvT  = sym(g_WvT);
    float* WpT  = sym(g_WpT);

    const int MS = B_ * S_;               // 65536
    const float inv_sqrt_h = 0.044194173824159216f;  // 1/sqrt(512)

    // weight transposes (B operand of NT gemm = W^T)
    {
        int n1 = D_ * H_;
        transpose_k<<<(n1 + 255) / 256, 256>>>(Wq, WqT, D_, H_);
        transpose_k<<<(n1 + 255) / 256, 256>>>(Wk, WkT, D_, H_);
        transpose_k<<<(n1 + 255) / 256, 256>>>(Wv, WvT, D_, H_);
        transpose_k<<<(n1 + 255) / 256, 256>>>(Wp, WpT, H_, D_);
    }

    // q = rgb @ Wq + bq
    gemm_tf32<<<dim3(H_ / 128, MS / 128, 1), 256>>>(
        rgb, 0, WqT, 0, q, 0, MS, H_, D_, 1.f, bq, nullptr);
    // k = pose @ Wk + bk
    gemm_tf32<<<dim3(H_ / 128, MS / 128, 1), 256>>>(
        pose, 0, WkT, 0, k, 0, MS, H_, D_, 1.f, bk, nullptr);
    // vT[b][h][s] = (pose_b @ Wv + bv)^T
    gemm_tf32<<<dim3(S_ / 128, H_ / 128, B_), 256>>>(
        WvT, 0, pose, (long)S_ * D_, vT, (long)H_ * S_,
        H_, S_, D_, 1.f, nullptr, bv);

    // scores[b][q][k] = q_b . k_b / sqrt(H)
    gemm_tf32<<<dim3(S_ / 128, S_ / 128, B_), 256>>>(
        q, (long)S_ * H_, k, (long)S_ * H_, att, (long)S_ * S_,
        S_, S_, H_, inv_sqrt_h, nullptr, nullptr);

    // softmax rows
    softmax2048<<<B_ * S_, 256>>>(att);

    // out[b][q][h] = attn_b @ v_b
    gemm_tf32<<<dim3(H_ / 128, S_ / 128, B_), 256>>>(
        att, (long)S_ * S_, vT, (long)H_ * S_, o, (long)S_ * H_,
        S_, H_, S_, 1.f, nullptr, nullptr);

    // proj = out @ Wp + bp  (N=400 tail guarded)
    gemm_tf32<<<dim3((D_ + 127) / 128, MS / 128, 1), 256>>>(
        o, 0, WpT, 0, proj, 0, MS, D_, H_, 1.f, bp, nullptr);

    // fused = LN(rgb + gate*proj)
    ln_epilogue<<<B_ * S_, 128>>>(proj, rgb, gate, gamma, beta, out);
}